// round 15
// baseline (speedup 1.0000x reference)
#include <cuda_runtime.h>
#include <math_constants.h>
#include <cstdint>

#define B_    8
#define L_    4096
#define DM_   512
#define H_    8
#define DK_   64
#define DV_   64
#define U_    41
#define BH_   (B_*H_)
#define NCH_  8
#define NCH2_ 16
#define CHUNK_ (L_/NCH_)
#define PREC_ 68
#define EPS_  1e-5f

// ---------------- scratch ----------------------------------------------------
__device__ float g_Q[B_*L_*DM_];
__device__ float g_K[B_*L_*DM_];
__device__ float g_V[B_*L_*DM_];
__device__ float g_Wt[3*DM_*DM_];
__device__ float g_M[BH_*L_];
__device__ int   g_idx[BH_*U_];
__device__ float g_cval[BH_*8*U_];
__device__ int   g_cidx[BH_*8*U_];
__device__ float g_vals[BH_*U_*DV_];
__device__ float g_vmean[BH_*DV_];
__device__ float g_obase4[4][B_*DM_];
__device__ __align__(16) float g_part[BH_*NCH2_*U_*PREC_];

// ---------------- helpers ------------------------------------------------------
__device__ __forceinline__ uint32_t smem_u32(const void* p) {
    uint32_t a;
    asm("{ .reg .u64 t; cvta.to.shared.u64 t, %1; cvt.u32.u64 %0, t; }" : "=r"(a) : "l"(p));
    return a;
}
#define CP_ASYNC_CG(dst, src) \
    asm volatile("cp.async.cg.shared.global [%0], [%1], 16;" :: "r"(dst), "l"(src) : "memory")
#define CP_COMMIT() asm volatile("cp.async.commit_group;" ::: "memory")
#define CP_WAIT1()  asm volatile("cp.async.wait_group 1;" ::: "memory")
#define CP_WAIT0()  asm volatile("cp.async.wait_group 0;" ::: "memory")

__device__ __forceinline__ uint32_t packbf(float e0, float e1) {
    uint32_t r;
    asm("cvt.rn.bf16x2.f32 %0, %1, %2;" : "=r"(r) : "f"(e1), "f"(e0));
    return r;
}
__device__ __forceinline__ void splitbf(float2 x, uint32_t& h, uint32_t& l) {
    h = packbf(x.x, x.y);
    float r0 = x.x - __uint_as_float(h << 16);
    float r1 = x.y - __uint_as_float(h & 0xffff0000u);
    l = packbf(r0, r1);
}

#define MMA_BF16(c, a, b) \
    asm volatile("mma.sync.aligned.m16n8k16.row.col.f32.bf16.bf16.f32 " \
        "{%0,%1,%2,%3}, {%4,%5,%6,%7}, {%8,%9}, {%0,%1,%2,%3};" \
        : "+f"((c)[0]), "+f"((c)[1]), "+f"((c)[2]), "+f"((c)[3]) \
        : "r"((a)[0]), "r"((a)[1]), "r"((a)[2]), "r"((a)[3]), \
          "r"((b)[0]), "r"((b)[1]))

// ---------------- W transpose (fp32 only), all 3 weights ------------------------
__global__ __launch_bounds__(256) void transW_kernel(
    const float* __restrict__ W0, const float* __restrict__ W1,
    const float* __restrict__ W2)
{
    __shared__ float tile[32][33];
    const float* W = (blockIdx.z == 0) ? W0 : (blockIdx.z == 1) ? W1 : W2;
    float* dst = g_Wt + (size_t)blockIdx.z * DM_ * DM_;
    int bx = blockIdx.x * 32;
    int by = blockIdx.y * 32;
    int tx = threadIdx.x & 31, ty = threadIdx.x >> 5;
#pragma unroll
    for (int i = 0; i < 4; i++)
        tile[ty + 8 * i][tx] = __ldg(&W[(size_t)(by + ty + 8 * i) * 512 + bx + tx]);
    __syncthreads();
#pragma unroll
    for (int i = 0; i < 4; i++)
        dst[(size_t)(bx + ty + 8 * i) * 512 + by + tx] = tile[tx][ty + 8 * i];
}

// ---------------- HMMA bf16 GEMM: BK=16, 2 CTAs/SM -------------------------------
#define PADK 20
#define MATF (128 * PADK)              // 2560 floats
#define STAGEF (2 * MATF)              // 5120
#define GSMEM_BYTES (2 * STAGEF * 4)   // 40960 -> 2 CTAs/SM

__device__ __forceinline__ void g_load_stage(
    float* sm, int stage, int c, int tid,
    const float* __restrict__ A, const float* __restrict__ Bt)
{
    float* dst = sm + stage * STAGEF;
#pragma unroll
    for (int i = 0; i < 2; i++) {
        int idx = i * 256 + tid;           // 0..511 (128 rows x 4 float4)
        int row = idx >> 2, q = idx & 3;
        CP_ASYNC_CG(smem_u32(dst + row * PADK + q * 4),
                    A + (size_t)row * 512 + c * 16 + q * 4);
    }
#pragma unroll
    for (int i = 0; i < 2; i++) {
        int idx = i * 256 + tid;
        int row = idx >> 2, q = idx & 3;
        CP_ASYNC_CG(smem_u32(dst + MATF + row * PADK + q * 4),
                    Bt + (size_t)row * 512 + c * 16 + q * 4);
    }
    CP_COMMIT();
}

__global__ __launch_bounds__(256, 2) void gemm3_hmma(
    const float* __restrict__ inQ, const float* __restrict__ inK,
    const float* __restrict__ inV, int base, int rowbase)
{
    extern __shared__ float sm[];
    const int tid = threadIdx.x;
    const int wid = tid >> 5, lane = tid & 31;
    const int g = lane >> 2, tg = lane & 3;
    const int wm = wid & 1, wn = wid >> 1;
    const int row0 = rowbase + blockIdx.y * 128, col0 = blockIdx.x * 128;
    const int which = base + blockIdx.z;
    const bool full = (which != 2);

    const float* Asrc = (which == 0) ? inQ : (which == 1) ? inK : inV;
    const float* A  = Asrc + (size_t)row0 * 512;
    const float* Bt = g_Wt + (size_t)which * DM_ * DM_ + (size_t)col0 * 512;
    float* C = (which == 0) ? g_Q : (which == 1) ? g_K : g_V;

    float acc[4][4][4];
#pragma unroll
    for (int i = 0; i < 4; i++)
#pragma unroll
        for (int j = 0; j < 4; j++)
#pragma unroll
            for (int r = 0; r < 4; r++) acc[i][j][r] = 0.f;

    g_load_stage(sm, 0, 0, tid, A, Bt);

    for (int c = 0; c < 32; c++) {
        const int buf = c & 1;
        if (c < 31) g_load_stage(sm, buf ^ 1, c + 1, tid, A, Bt);
        if (c < 31) { CP_WAIT1(); } else { CP_WAIT0(); }
        __syncthreads();

        const float* sA = sm + buf * STAGEF;
        const float* sB = sA + MATF;

        // A fragments for one k16 step
        uint32_t ah[4][4], al[4][4];
#pragma unroll
        for (int i = 0; i < 4; i++) {
            int r = wm * 64 + i * 16 + g;
            float2 x0 = *(const float2*)&sA[r * PADK + 2 * tg];
            float2 x1 = *(const float2*)&sA[(r + 8) * PADK + 2 * tg];
            float2 x2 = *(const float2*)&sA[r * PADK + 2 * tg + 8];
            float2 x3 = *(const float2*)&sA[(r + 8) * PADK + 2 * tg + 8];
            if (full) {
                splitbf(x0, ah[i][0], al[i][0]);
                splitbf(x1, ah[i][1], al[i][1]);
                splitbf(x2, ah[i][2], al[i][2]);
                splitbf(x3, ah[i][3], al[i][3]);
            } else {
                ah[i][0] = packbf(x0.x, x0.y);
                ah[i][1] = packbf(x1.x, x1.y);
                ah[i][2] = packbf(x2.x, x2.y);
                ah[i][3] = packbf(x3.x, x3.y);
            }
        }

        // B fragments in two j-halves (halved live registers)
#pragma unroll
        for (int jh = 0; jh < 2; jh++) {
            uint32_t bh[2][2], bl[2][2];
#pragma unroll
            for (int j = 0; j < 2; j++) {
                int n = wn * 32 + (jh * 2 + j) * 8 + g;
                float2 y0 = *(const float2*)&sB[n * PADK + 2 * tg];
                float2 y1 = *(const float2*)&sB[n * PADK + 2 * tg + 8];
                if (full) {
                    splitbf(y0, bh[j][0], bl[j][0]);
                    splitbf(y1, bh[j][1], bl[j][1]);
                } else {
                    bh[j][0] = packbf(y0.x, y0.y);
                    bh[j][1] = packbf(y1.x, y1.y);
                }
            }
#pragma unroll
            for (int i = 0; i < 4; i++)
#pragma unroll
                for (int j = 0; j < 2; j++)
                    MMA_BF16(acc[i][jh * 2 + j], ah[i], bh[j]);
            if (full) {
#pragma unroll
                for (int i = 0; i < 4; i++)
#pragma unroll
                    for (int j = 0; j < 2; j++)
                        MMA_BF16(acc[i][jh * 2 + j], ah[i], bl[j]);
#pragma unroll
                for (int i = 0; i < 4; i++)
#pragma unroll
                    for (int j = 0; j < 2; j++)
                        MMA_BF16(acc[i][jh * 2 + j], al[i], bh[j]);
            }
        }
        __syncthreads();
    }

#pragma unroll
    for (int i = 0; i < 4; i++) {
#pragma unroll
        for (int j = 0; j < 4; j++) {
            int row = row0 + wm * 64 + i * 16 + g;
            int col = col0 + wn * 32 + j * 8 + tg * 2;
            float2 v0 = make_float2(acc[i][j][0], acc[i][j][1]);
            float2 v1 = make_float2(acc[i][j][2], acc[i][j][3]);
            *(float2*)(C + (size_t)row * 512 + col) = v0;
            *(float2*)(C + (size_t)(row + 8) * 512 + col) = v1;
        }
    }
}

// ---------------- QK_samp -> M (batch-sliced) -------------------------------------
__global__ __launch_bounds__(256) void qkm3_kernel(const int* __restrict__ isamp,
                                                   int boff)
{
    int gw   = ((boff + blockIdx.x) * 256 + threadIdx.x) >> 5;
    int lane = threadIdx.x & 31;
    int l = gw & (L_ - 1);
    int b = gw >> 12;

    const float4* qb = (const float4*)(g_Q + ((size_t)(b * L_ + l)) * DM_);
    float4 q0 = qb[lane], q1 = qb[lane + 32], q2 = qb[lane + 64], q3 = qb[lane + 96];

    float smax0 = -CUDART_INF_F, smax1 = -CUDART_INF_F, smax2 = -CUDART_INF_F, smax3 = -CUDART_INF_F;
    float ssum0 = 0.f, ssum1 = 0.f, ssum2 = 0.f, ssum3 = 0.f;
    const int* ip = isamp + l * U_;

#pragma unroll 2
    for (int u = 0; u < U_; u++) {
        int j = __ldg(ip + u);
        const float4* kb = (const float4*)(g_K + ((size_t)(b * L_ + j)) * DM_);
        float4 k0 = kb[lane], k1 = kb[lane + 32], k2 = kb[lane + 64], k3 = kb[lane + 96];
        float s0 = q0.x * k0.x; s0 = fmaf(q0.y, k0.y, s0); s0 = fmaf(q0.z, k0.z, s0); s0 = fmaf(q0.w, k0.w, s0);
        float s1 = q1.x * k1.x; s1 = fmaf(q1.y, k1.y, s1); s1 = fmaf(q1.z, k1.z, s1); s1 = fmaf(q1.w, k1.w, s1);
        float s2 = q2.x * k2.x; s2 = fmaf(q2.y, k2.y, s2); s2 = fmaf(q2.z, k2.z, s2); s2 = fmaf(q2.w, k2.w, s2);
        float s3 = q3.x * k3.x; s3 = fmaf(q3.y, k3.y, s3); s3 = fmaf(q3.z, k3.z, s3); s3 = fmaf(q3.w, k3.w, s3);
#pragma unroll
        for (int m = 1; m <= 8; m <<= 1) {
            s0 += __shfl_xor_sync(0xffffffffu, s0, m);
            s1 += __shfl_xor_sync(0xffffffffu, s1, m);
            s2 += __shfl_xor_sync(0xffffffffu, s2, m);
            s3 += __shfl_xor_sync(0xffffffffu, s3, m);
        }
        smax0 = fmaxf(smax0, s0); ssum0 += s0;
        smax1 = fmaxf(smax1, s1); ssum1 += s1;
        smax2 = fmaxf(smax2, s2); ssum2 += s2;
        smax3 = fmaxf(smax3, s3); ssum3 += s3;
    }
    if ((lane & 15) == 0) {
        int g = lane >> 4;
        size_t base = ((size_t)b * 8) * L_ + l;
        g_M[base + (size_t)(g + 0) * L_] = smax0 - ssum0 * (1.0f / U_);
        g_M[base + (size_t)(g + 2) * L_] = smax1 - ssum1 * (1.0f / U_);
        g_M[base + (size_t)(g + 4) * L_] = smax2 - ssum2 * (1.0f / U_);
        g_M[base + (size_t)(g + 6) * L_] = smax3 - ssum3 * (1.0f / U_);
    }
}

// ---------------- top-k phase A (bh-sliced) ---------------------------------------
__global__ __launch_bounds__(256) void topkA_kernel(int bhoff)
{
    int slice = blockIdx.x, bh = bhoff + blockIdx.y;
    __shared__ float sv[512];
    __shared__ float wv[8];
    __shared__ int   wi[8];
    int tid = threadIdx.x, lane = tid & 31, w = tid >> 5;

    sv[tid]       = g_M[bh * L_ + slice * 512 + tid];
    sv[tid + 256] = g_M[bh * L_ + slice * 512 + tid + 256];
    __syncthreads();

    for (int it = 0; it < U_; it++) {
        float v0 = sv[tid], v1 = sv[tid + 256];
        float bv; int bi;
        if (v1 > v0) { bv = v1; bi = tid + 256; } else { bv = v0; bi = tid; }
#pragma unroll
        for (int o = 16; o > 0; o >>= 1) {
            float ov = __shfl_xor_sync(0xffffffffu, bv, o);
            int   oi = __shfl_xor_sync(0xffffffffu, bi, o);
            if (ov > bv || (ov == bv && oi < bi)) { bv = ov; bi = oi; }
        }
        if (lane == 0) { wv[w] = bv; wi[w] = bi; }
        __syncthreads();
        if (tid == 0) {
            float fv = wv[0]; int fi = wi[0];
#pragma unroll
            for (int k = 1; k < 8; k++) {
                if (wv[k] > fv || (wv[k] == fv && wi[k] < fi)) { fv = wv[k]; fi = wi[k]; }
            }
            sv[fi] = -CUDART_INF_F;
            g_cval[(bh * 8 + slice) * U_ + it] = fv;
            g_cidx[(bh * 8 + slice) * U_ + it] = slice * 512 + fi;
        }
        __syncthreads();
    }
}

// ---------------- top-k phase B (bh-sliced) ---------------------------------------
__global__ __launch_bounds__(256) void topkB_kernel(int bhoff)
{
    int bh = bhoff + blockIdx.x;
    __shared__ float sv[512];
    __shared__ int   si[512];
    __shared__ float wv[8];
    __shared__ int   wi[8];
    int tid = threadIdx.x, lane = tid & 31, w = tid >> 5;

    const int NC = 8 * U_;
#pragma unroll
    for (int r = 0; r < 2; r++) {
        int i = tid + 256 * r;
        if (i < NC) {
            sv[i] = g_cval[bh * NC + i];
            si[i] = g_cidx[bh * NC + i];
        } else if (i < 512) {
            sv[i] = -CUDART_INF_F;
            si[i] = 0x7fffffff;
        }
    }
    __syncthreads();

    for (int it = 0; it < U_; it++) {
        float v0 = sv[tid], v1 = sv[tid + 256];
        int   i0 = si[tid], i1 = si[tid + 256];
        float bv; int bi, bslot;
        if (v1 > v0 || (v1 == v0 && i1 < i0)) { bv = v1; bi = i1; bslot = tid + 256; }
        else                                   { bv = v0; bi = i0; bslot = tid; }
#pragma unroll
        for (int o = 16; o > 0; o >>= 1) {
            float ov = __shfl_xor_sync(0xffffffffu, bv, o);
            int   oi = __shfl_xor_sync(0xffffffffu, bi, o);
            int   os = __shfl_xor_sync(0xffffffffu, bslot, o);
            if (ov > bv || (ov == bv && oi < bi)) { bv = ov; bi = oi; bslot = os; }
        }
        if (lane == 0) { wv[w] = bv; wi[w] = bslot; }
        __syncthreads();
        if (tid == 0) {
            float fv = wv[0]; int fslot = wi[0];
#pragma unroll
            for (int k = 1; k < 8; k++) {
                int s2 = wi[k];
                if (wv[k] > fv || (wv[k] == fv && si[s2] < si[fslot])) { fv = wv[k]; fslot = s2; }
            }
            g_idx[bh * U_ + it] = si[fslot];
            sv[fslot] = -CUDART_INF_F;
            si[fslot] = 0x7fffffff;
        }
        __syncthreads();
    }
}

// ---------------- V mean per (b,h): 1024 threads, 16-way L-split ------------------
__global__ __launch_bounds__(1024) void vmean_kernel(int bhoff)
{
    int bh = bhoff + blockIdx.x;
    int b = bh >> 3, h = bh & 7;
    int tid = threadIdx.x;
    int d = tid & 63, g = tid >> 6;
    float sum = 0.f;
#pragma unroll 4
    for (int l = g; l < L_; l += 16)
        sum += g_V[((size_t)(b * L_ + l)) * DM_ + h * DK_ + d];
    __shared__ float red[16][64];
    red[g][d] = sum;
    __syncthreads();
    if (g == 0) {
        float t = 0.f;
#pragma unroll
        for (int k = 0; k < 16; k++) t += red[k][d];
        g_vmean[bh * 64 + d] = t * (1.0f / L_);
    }
}

// ---------------- obase partials: per-kc buffers, plain stores --------------------
__global__ __launch_bounds__(256) void obase_part(const float* __restrict__ Wfc,
                                                  int boff)
{
    int b = boff + blockIdx.x;
    int kc = blockIdx.y;
    int tid = threadIdx.x;
    __shared__ float vm[128];
    if (tid < 128) vm[tid] = g_vmean[b * 512 + kc * 128 + tid];
    __syncthreads();
    float a0 = 0.f, a1 = 0.f;
    const float2* W2 = (const float2*)Wfc + tid + (size_t)(kc * 128) * 256;
#pragma unroll 8
    for (int r = 0; r < 128; r++) {
        float2 w = __ldg(W2 + (size_t)r * 256);
        float v = vm[r];
        a0 = fmaf(v, w.x, a0);
        a1 = fmaf(v, w.y, a1);
    }
    g_obase4[kc][b * 512 + 2 * tid]     = a0;
    g_obase4[kc][b * 512 + 2 * tid + 1] = a1;
}

__global__ __launch_bounds__(256) void out_assemble(const float* __restrict__ inQ,
                                                    float* __restrict__ out,
                                                    int i4off)
{
    int i4 = i4off + blockIdx.x * 256 + threadIdx.x;
    int b  = i4 >> 19;
    int c4 = i4 & 127;
    float4 x = ((const float4*)inQ)[i4];
#pragma unroll
    for (int kc = 0; kc < 4; kc++) {
        float4 o = __ldg((const float4*)g_obase4[kc] + (b << 7) + c4);
        x.x += o.x; x.y += o.y; x.z += o.z; x.w += o.w;
    }
    ((float4*)out)[i4] = x;
}

// ---------------- sparse attention: 16-lane groups (bh-sliced) --------------------
__global__ __launch_bounds__(256) void attn_partial(int bhoff)
{
    int ch = blockIdx.x, bh = bhoff + blockIdx.y;
    int b = bh >> 3, h = bh & 7;
    int tid = threadIdx.x, lane = tid & 31, w = tid >> 5;
    int grp = lane >> 4, l4 = lane & 15;

    __shared__ float qs[U_ * DK_];
    __shared__ float Ks[64 * 68];
    __shared__ float Vs[64 * 68];

    for (int i = tid; i < U_ * DK_; i += 256) {
        int u = i >> 6, d = i & 63;
        int l = g_idx[bh * U_ + u];
        qs[i] = g_Q[((size_t)(b * L_ + l)) * DM_ + h * DK_ + d];
    }
    __syncthreads();

    const int nu = (w == 0) ? 6 : 5;
    float4 q4[6], a4[6];
    float m[6], ss[6];
#pragma unroll
    for (int k = 0; k < 6; k++) {
        if (k < nu) {
            int u = w + 8 * k;
            q4[k] = *(const float4*)&qs[u * 64 + 4 * l4];
        } else {
            q4[k] = make_float4(0.f, 0.f, 0.f, 0.f);
        }
        m[k] = -CUDART_INF_F; ss[k] = 0.f;
        a4[k] = make_float4(0.f, 0.f, 0.f, 0.f);
    }

    const int jbase0 = ch * CHUNK_;
    for (int t = 0; t < CHUNK_ / 64; t++) {
        __syncthreads();
        int jb = jbase0 + t * 64;
        const float4* Kg = (const float4*)(g_K + ((size_t)(b * L_ + jb)) * DM_ + h * DK_);
        const float4* Vg = (const float4*)(g_V + ((size_t)(b * L_ + jb)) * DM_ + h * DK_);
#pragma unroll
        for (int r = 0; r < 4; r++) {
            int idx = tid + 256 * r;
            int row = idx >> 4, cq = idx & 15;
            float4 kv = Kg[(size_t)row * (DM_ / 4) + cq];
            *(float4*)&Ks[row * 68 + cq * 4] = kv;
            float4 vv = Vg[(size_t)row * (DM_ / 4) + cq];
            *(float4*)&Vs[row * 68 + cq * 4] = vv;
        }
        __syncthreads();

#pragma unroll 2
        for (int jj2 = 0; jj2 < 32; jj2++) {
            int jj = jj2 * 2 + grp;
            float4 k4 = *(const float4*)&Ks[jj * 68 + 4 * l4];
            float4 v4 = *(const float4*)&Vs[jj * 68 + 4 * l4];
            float sc[6];
#pragma unroll
            for (int k = 0; k < 6; k++) {
                float s = q4[k].x * k4.x;
                s = fmaf(q4[k].y, k4.y, s);
                s = fmaf(q4[k].z, k4.z, s);
                s = fmaf(q4[k].w, k4.w, s);
                sc[k] = s;
            }
#pragma unroll
            for (int o = 1; o <= 8; o <<= 1) {
#pragma unroll
                for (int k = 0; k < 6; k++)
                    sc[k] += __shfl_xor_sync(0xffffffffu, sc[k], o);
            }
#pragma unroll
            for (int k = 0; k < 6; k++) {
                float s = sc[k] * 0.125f;
                float mn = fmaxf(m[k], s);
                float ea = __expf(s - mn);
                float eb = __expf(m[k] - mn);
                ss[k] = ss[k] * eb + ea;
                a4[k].x = a4[k].x * eb + ea * v4.x;
                a4[k].y = a4[k].y * eb + ea * v4.y;
                a4[k].z = a4[k].z * eb + ea * v4.z;
                a4[k].w = a4[k].w * eb + ea * v4.w;
                m[k] = mn;
            }
        }
    }

    const int c2 = ch * 2 + grp;
#pragma unroll
    for (int k = 0; k < 6; k++) {
        if (k < nu) {
            int u = w + 8 * k;
            size_t base = ((size_t)(bh * NCH2_ + c2) * U_ + u) * PREC_;
            *(float4*)&g_part[base + 4 * l4] = a4[k];
            if (l4 == 0) { g_part[base + 64] = m[k]; g_part[base + 65] = ss[k]; }
        }
    }
}

// ---------------- combine split-L partials (bh-sliced) ----------------------------
__global__ __launch_bounds__(256) void attn_combine(int bhoff)
{
    int gw = (blockIdx.x * blockDim.x + threadIdx.x) >> 5;
    int lane = threadIdx.x & 31;
    if (gw >= 32 * U_) return;
    int bh = bhoff + gw / U_, u = gw % U_;

    float M = -CUDART_INF_F;
#pragma unroll
    for (int ch = 0; ch < NCH2_; ch++)
        M = fmaxf(M, g_part[((size_t)(bh * NCH2_ + ch) * U_ + u) * PREC_ + 64]);
    float S = 0.f, a0 = 0.f, a1 = 0.f;
#pragma unroll
    for (int ch = 0; ch < NCH2_; ch++) {
        size_t base = ((size_t)(bh * NCH2_ + ch) * U_ + u) * PREC_;
        float f = __expf(g_part[base + 64] - M);
        S  += g_part[base + 65] * f;
        a0 += g_part[base + 2 * lane] * f;
        a1 += g_part[base + 2 * lane + 1] * f;
    }
    float inv = 1.0f / S;
    size_t gv = (size_t)(bh * U_ + u) * 64;
    g_vals[gv + 2 * lane]     = a0 * inv;
    g_vals[gv + 2 * lane + 1] = a1 * inv;
}

__global__ __launch_bounds__(128) void correction_kernel(float* __restrict__ out,
                                                         const float* __restrict__ Wfc,
                                                         int guoff)
{
    int gu = guoff + blockIdx.x;
    int bh = gu / U_;
    int b = bh >> 3, h = bh & 7;
    int l = g_idx[gu];
    int tid = threadIdx.x;

    __shared__ float delta[64];
    if (tid < 64)
        delta[tid] = g_vals[(size_t)gu * 64 + tid] - g_vmean[bh * 64 + tid];
    __syncthreads();

    float4 acc = make_float4(0.f, 0.f, 0.f, 0.f);
    const float4* W4 = (const float4*)Wfc + (size_t)(h * 64) * 128 + tid;
#pragma unroll 8
    for (int k = 0; k < 64; k++) {
        float d = delta[k];
        float4 w = __ldg(W4 + (size_t)k * 128);
        acc.x = fmaf(d, w.x, acc.x);
        acc.y = fmaf(d, w.y, acc.y);
        acc.z = fmaf(d, w.z, acc.z);
        acc.w = fmaf(d, w.w, acc.w);
    }
    float* o = out + ((size_t)(b * L_ + l)) * 512 + tid * 4;
    atomicAdd(o + 0, acc.x);
    atomicAdd(o + 1, acc.y);
    atomicAdd(o + 2, acc.z);
    atomicAdd(o + 3, acc.w);
}

// ---------------- LayerNorm (row-sliced) ------------------------------------------
__global__ __launch_bounds__(128) void ln_kernel(float* __restrict__ out,
                                                 const float* __restrict__ gamma,
                                                 const float* __restrict__ beta,
                                                 int rowoff)
{
    int row = rowoff + blockIdx.x, tid = threadIdx.x;
    float4 x = ((const float4*)out)[(size_t)row * 128 + tid];
    float s  = x.x + x.y + x.z + x.w;
    float sq = x.x * x.x + x.y * x.y + x.z * x.z + x.w * x.w;
#pragma unroll
    for (int o = 16; o > 0; o >>= 1) {
        s  += __shfl_xor_sync(0xffffffffu, s, o);
        sq += __shfl_xor_sync(0xffffffffu, sq, o);
    }
    __shared__ float sh[8];
    int w = tid >> 5, lane = tid & 31;
    if (lane == 0) { sh[w] = s; sh[4 + w] = sq; }
    __syncthreads();
    s  = sh[0] + sh[1] + sh[2] + sh[3];
    sq = sh[4] + sh[5] + sh[6] + sh[7];
    float mu  = s * (1.0f / 512.0f);
    float var = sq * (1.0f / 512.0f) - mu * mu;
    float r   = rsqrtf(var + EPS_);
    float4 gg = ((const float4*)gamma)[tid];
    float4 bb = ((const float4*)beta)[tid];
    float4 y;
    y.x = gg.x * (x.x - mu) * r + bb.x;
    y.y = gg.y * (x.y - mu) * r + bb.y;
    y.z = gg.z * (x.z - mu) * r + bb.z;
    y.w = gg.w * (x.w - mu) * r + bb.w;
    ((float4*)out)[(size_t)row * 128 + tid] = y;
}

// ---------------- launch ------------------------------------------------------------
extern "C" void kernel_launch(void* const* d_in, const int* in_sizes, int n_in,
                              void* d_out, int out_size)
{
    const float* inQ   = (const float*)d_in[0];
    const float* inK   = (const float*)d_in[1];
    const float* inV   = (const float*)d_in[2];
    const float* WQ    = (const float*)d_in[3];
    const float* WK    = (const float*)d_in[4];
    const float* WV    = (const float*)d_in[5];
    const float* Wfc   = (const float*)d_in[6];
    const float* gamma = (const float*)d_in[7];
    const float* beta  = (const float*)d_in[8];
    const int*   isamp = (const int*)d_in[9];
    float* out = (float*)d_out;

    static cudaStream_t s2, s3, s4;
    static cudaEvent_t evGa, evVa, evGb, evVb, evQb, evOAa, evOAb, evH1;
    static bool init = false;
    if (!init) {
        cudaStreamCreateWithFlags(&s2, cudaStreamNonBlocking);
        cudaStreamCreateWithFlags(&s3, cudaStreamNonBlocking);
        cudaStreamCreateWithFlags(&s4, cudaStreamNonBlocking);
        cudaEventCreateWithFlags(&evGa, cudaEventDisableTiming);
        cudaEventCreateWithFlags(&evVa, cudaEventDisableTiming);
        cudaEventCreateWithFlags(&evGb, cudaEventDisableTiming);
        cudaEventCreateWithFlags(&evVb, cudaEventDisableTiming);
        cudaEventCreateWithFlags(&evQb, cudaEventDisableTiming);
        cudaEventCreateWithFlags(&evOAa, cudaEventDisableTiming);
        cudaEventCreateWithFlags(&evOAb, cudaEventDisableTiming);
        cudaEventCreateWithFlags(&evH1, cudaEventDisableTiming);
        cudaFuncSetAttribute(gemm3_hmma, cudaFuncAttributeMaxDynamicSharedMemorySize,
                             GSMEM_BYTES);
        init = true;
    }

    const int cmbBlocks = (32 * U_ * 32 + 255) / 256;

    // ---- main: ALL tensor work back-to-back ----
    transW_kernel<<<dim3(16, 16, 3), 256>>>(WQ, WK, WV);
    gemm3_hmma<<<dim3(4, 128, 2), 256, GSMEM_BYTES>>>(inQ, inK, inV, 0, 0);       // QK b0-3
    cudaEventRecord(evGa, 0);
    gemm3_hmma<<<dim3(4, 128, 1), 256, GSMEM_BYTES>>>(inQ, inK, inV, 2, 0);       // V  b0-3
    cudaEventRecord(evVa, 0);
    gemm3_hmma<<<dim3(4, 128, 2), 256, GSMEM_BYTES>>>(inQ, inK, inV, 0, 16384);   // QK b4-7
    cudaEventRecord(evGb, 0);
    gemm3_hmma<<<dim3(4, 128, 1), 256, GSMEM_BYTES>>>(inQ, inK, inV, 2, 16384);   // V  b4-7
    cudaEventRecord(evVb, 0);

    // ---- s2: V-branch halves ----
    cudaStreamWaitEvent(s2, evVa, 0);
    vmean_kernel<<<32, 1024, 0, s2>>>(0);
    obase_part<<<dim3(4, 4), 256, 0, s2>>>(Wfc, 0);
    out_assemble<<<8192, 256, 0, s2>>>(inQ, out, 0);
    cudaEventRecord(evOAa, s2);
    cudaStreamWaitEvent(s2, evVb, 0);
    vmean_kernel<<<32, 1024, 0, s2>>>(32);
    obase_part<<<dim3(4, 4), 256, 0, s2>>>(Wfc, 4);
    out_assemble<<<8192, 256, 0, s2>>>(inQ, out, 8192 * 256);
    cudaEventRecord(evOAb, s2);

    // ---- s4: qkm second half (overlaps gemmV b4-7) ----
    cudaStreamWaitEvent(s4, evGb, 0);
    qkm3_kernel<<<2048, 256, 0, s4>>>(isamp, 2048);
    cudaEventRecord(evQb, s4);

    // ---- s3: first-half tail (bh 0-31, rows 0-16383) ----
    cudaStreamWaitEvent(s3, evGa, 0);
    qkm3_kernel<<<2048, 256, 0, s3>>>(isamp, 0);
    topkA_kernel<<<dim3(8, 32), 256, 0, s3>>>(0);
    topkB_kernel<<<32, 256, 0, s3>>>(0);
    cudaStreamWaitEvent(s3, evVa, 0);
    attn_partial<<<dim3(NCH_, 32), 256, 0, s3>>>(0);
    attn_combine<<<cmbBlocks, 256, 0, s3>>>(0);
    cudaStreamWaitEvent(s3, evOAa, 0);
    correction_kernel<<<32 * U_, 128, 0, s3>>>(out, Wfc, 0);
    ln_kernel<<<16384, 128, 0, s3>>>(out, gamma, beta, 0);
    cudaEventRecord(evH1, s3);

    // ---- main: second-half tail (bh 32-63, rows 16384-32767) ----
    cudaStreamWaitEvent(0, evQb, 0);
    topkA_kernel<<<dim3(8, 32), 256>>>(32);
    topkB_kernel<<<32, 256>>>(32);
    attn_partial<<<dim3(NCH_, 32), 256>>>(32);
    attn_combine<<<cmbBlocks, 256>>>(32);
    cudaStreamWaitEvent(0, evOAb, 0);
    correction_kernel<<<32 * U_, 128>>>(out, Wfc, 32 * U_);
    ln_kernel<<<16384, 128>>>(out, gamma, beta, 16384);

    // ---- join ----
    cudaStreamWaitEvent(0, evH1, 0);
}

// round 16
// speedup vs baseline: 1.1457x; 1.1457x over previous
#include <cuda_runtime.h>
#include <math_constants.h>
#include <cstdint>

#define B_    8
#define L_    4096
#define DM_   512
#define H_    8
#define DK_   64
#define DV_   64
#define U_    41
#define BH_   (B_*H_)
#define NCH_  8
#define NCH2_ 16
#define CHUNK_ (L_/NCH_)
#define PREC_ 68
#define EPS_  1e-5f

// ---------------- scratch ----------------------------------------------------
__device__ float g_Q[B_*L_*DM_];
__device__ float g_K[B_*L_*DM_];
__device__ float g_V[B_*L_*DM_];
__device__ float g_Wt[3*DM_*DM_];
__device__ float g_M[BH_*L_];
__device__ int   g_idx[BH_*U_];
__device__ float g_cval[BH_*8*U_];
__device__ int   g_cidx[BH_*8*U_];
__device__ float g_vals[BH_*U_*DV_];
__device__ float g_vmean[BH_*DV_];
__device__ float g_obase4[4][B_*DM_];
__device__ __align__(16) float g_part[BH_*NCH2_*U_*PREC_];

// ---------------- helpers ------------------------------------------------------
__device__ __forceinline__ uint32_t smem_u32(const void* p) {
    uint32_t a;
    asm("{ .reg .u64 t; cvta.to.shared.u64 t, %1; cvt.u32.u64 %0, t; }" : "=r"(a) : "l"(p));
    return a;
}
#define CP_ASYNC_CG(dst, src) \
    asm volatile("cp.async.cg.shared.global [%0], [%1], 16;" :: "r"(dst), "l"(src) : "memory")
#define CP_COMMIT() asm volatile("cp.async.commit_group;" ::: "memory")
#define CP_WAIT1()  asm volatile("cp.async.wait_group 1;" ::: "memory")
#define CP_WAIT0()  asm volatile("cp.async.wait_group 0;" ::: "memory")

__device__ __forceinline__ uint32_t packbf(float e0, float e1) {
    uint32_t r;
    asm("cvt.rn.bf16x2.f32 %0, %1, %2;" : "=r"(r) : "f"(e1), "f"(e0));
    return r;
}
__device__ __forceinline__ void splitbf(float2 x, uint32_t& h, uint32_t& l) {
    h = packbf(x.x, x.y);
    float r0 = x.x - __uint_as_float(h << 16);
    float r1 = x.y - __uint_as_float(h & 0xffff0000u);
    l = packbf(r0, r1);
}

#define MMA_BF16(c, a, b) \
    asm volatile("mma.sync.aligned.m16n8k16.row.col.f32.bf16.bf16.f32 " \
        "{%0,%1,%2,%3}, {%4,%5,%6,%7}, {%8,%9}, {%0,%1,%2,%3};" \
        : "+f"((c)[0]), "+f"((c)[1]), "+f"((c)[2]), "+f"((c)[3]) \
        : "r"((a)[0]), "r"((a)[1]), "r"((a)[2]), "r"((a)[3]), \
          "r"((b)[0]), "r"((b)[1]))

// ---------------- W transpose (fp32 only), all 3 weights ------------------------
__global__ __launch_bounds__(256) void transW_kernel(
    const float* __restrict__ W0, const float* __restrict__ W1,
    const float* __restrict__ W2)
{
    __shared__ float tile[32][33];
    const float* W = (blockIdx.z == 0) ? W0 : (blockIdx.z == 1) ? W1 : W2;
    float* dst = g_Wt + (size_t)blockIdx.z * DM_ * DM_;
    int bx = blockIdx.x * 32;
    int by = blockIdx.y * 32;
    int tx = threadIdx.x & 31, ty = threadIdx.x >> 5;
#pragma unroll
    for (int i = 0; i < 4; i++)
        tile[ty + 8 * i][tx] = __ldg(&W[(size_t)(by + ty + 8 * i) * 512 + bx + tx]);
    __syncthreads();
#pragma unroll
    for (int i = 0; i < 4; i++)
        dst[(size_t)(bx + ty + 8 * i) * 512 + by + tx] = tile[tx][ty + 8 * i];
}

// ---------------- HMMA bf16 GEMM: BK=32, 2 CTAs/SM -------------------------------
// BK32 keeps barriers at 32/CTA (long MMA bursts); jh-split B frags cap regs <=128;
// 2 x 80KB smem co-resident (sm_103a has ~228KB/SM).
#define PADK 40
#define MATF (128 * PADK)              // 5120 floats
#define STAGEF (2 * MATF)              // 10240
#define GSMEM_BYTES (2 * STAGEF * 4)   // 81920

__device__ __forceinline__ void g_load_stage(
    float* sm, int stage, int c, int tid,
    const float* __restrict__ A, const float* __restrict__ Bt)
{
    float* dst = sm + stage * STAGEF;
#pragma unroll
    for (int i = 0; i < 4; i++) {
        int idx = i * 256 + tid;
        int row = idx >> 3, q = idx & 7;
        CP_ASYNC_CG(smem_u32(dst + row * PADK + q * 4),
                    A + (size_t)row * 512 + c * 32 + q * 4);
    }
#pragma unroll
    for (int i = 0; i < 4; i++) {
        int idx = i * 256 + tid;
        int row = idx >> 3, q = idx & 7;
        CP_ASYNC_CG(smem_u32(dst + MATF + row * PADK + q * 4),
                    Bt + (size_t)row * 512 + c * 32 + q * 4);
    }
    CP_COMMIT();
}

__global__ __launch_bounds__(256, 2) void gemm3_hmma(
    const float* __restrict__ inQ, const float* __restrict__ inK,
    const float* __restrict__ inV, int base, int rowbase)
{
    extern __shared__ float sm[];
    const int tid = threadIdx.x;
    const int wid = tid >> 5, lane = tid & 31;
    const int g = lane >> 2, tg = lane & 3;
    const int wm = wid & 1, wn = wid >> 1;
    const int row0 = rowbase + blockIdx.y * 128, col0 = blockIdx.x * 128;
    const int which = base + blockIdx.z;
    const bool full = (which != 2);

    const float* Asrc = (which == 0) ? inQ : (which == 1) ? inK : inV;
    const float* A  = Asrc + (size_t)row0 * 512;
    const float* Bt = g_Wt + (size_t)which * DM_ * DM_ + (size_t)col0 * 512;
    float* C = (which == 0) ? g_Q : (which == 1) ? g_K : g_V;

    float acc[4][4][4];
#pragma unroll
    for (int i = 0; i < 4; i++)
#pragma unroll
        for (int j = 0; j < 4; j++)
#pragma unroll
            for (int r = 0; r < 4; r++) acc[i][j][r] = 0.f;

    g_load_stage(sm, 0, 0, tid, A, Bt);

    for (int c = 0; c < 16; c++) {
        const int buf = c & 1;
        if (c < 15) g_load_stage(sm, buf ^ 1, c + 1, tid, A, Bt);
        if (c < 15) { CP_WAIT1(); } else { CP_WAIT0(); }
        __syncthreads();

        const float* sA = sm + buf * STAGEF;
        const float* sB = sA + MATF;

#pragma unroll
        for (int ks = 0; ks < 2; ks++) {
            const int k0 = ks * 16;
            // A fragments for this k16 step
            uint32_t ah[4][4], al[4][4];
#pragma unroll
            for (int i = 0; i < 4; i++) {
                int r = wm * 64 + i * 16 + g;
                float2 x0 = *(const float2*)&sA[r * PADK + k0 + 2 * tg];
                float2 x1 = *(const float2*)&sA[(r + 8) * PADK + k0 + 2 * tg];
                float2 x2 = *(const float2*)&sA[r * PADK + k0 + 2 * tg + 8];
                float2 x3 = *(const float2*)&sA[(r + 8) * PADK + k0 + 2 * tg + 8];
                if (full) {
                    splitbf(x0, ah[i][0], al[i][0]);
                    splitbf(x1, ah[i][1], al[i][1]);
                    splitbf(x2, ah[i][2], al[i][2]);
                    splitbf(x3, ah[i][3], al[i][3]);
                } else {
                    ah[i][0] = packbf(x0.x, x0.y);
                    ah[i][1] = packbf(x1.x, x1.y);
                    ah[i][2] = packbf(x2.x, x2.y);
                    ah[i][3] = packbf(x3.x, x3.y);
                }
            }
            // B fragments in two j-halves (halved live registers)
#pragma unroll
            for (int jh = 0; jh < 2; jh++) {
                uint32_t bh[2][2], bl[2][2];
#pragma unroll
                for (int j = 0; j < 2; j++) {
                    int n = wn * 32 + (jh * 2 + j) * 8 + g;
                    float2 y0 = *(const float2*)&sB[n * PADK + k0 + 2 * tg];
                    float2 y1 = *(const float2*)&sB[n * PADK + k0 + 2 * tg + 8];
                    if (full) {
                        splitbf(y0, bh[j][0], bl[j][0]);
                        splitbf(y1, bh[j][1], bl[j][1]);
                    } else {
                        bh[j][0] = packbf(y0.x, y0.y);
                        bh[j][1] = packbf(y1.x, y1.y);
                    }
                }
#pragma unroll
                for (int i = 0; i < 4; i++)
#pragma unroll
                    for (int j = 0; j < 2; j++)
                        MMA_BF16(acc[i][jh * 2 + j], ah[i], bh[j]);
                if (full) {
#pragma unroll
                    for (int i = 0; i < 4; i++)
#pragma unroll
                        for (int j = 0; j < 2; j++)
                            MMA_BF16(acc[i][jh * 2 + j], ah[i], bl[j]);
#pragma unroll
                    for (int i = 0; i < 4; i++)
#pragma unroll
                        for (int j = 0; j < 2; j++)
                            MMA_BF16(acc[i][jh * 2 + j], al[i], bh[j]);
                }
            }
        }
        __syncthreads();
    }

#pragma unroll
    for (int i = 0; i < 4; i++) {
#pragma unroll
        for (int j = 0; j < 4; j++) {
            int row = row0 + wm * 64 + i * 16 + g;
            int col = col0 + wn * 32 + j * 8 + tg * 2;
            float2 v0 = make_float2(acc[i][j][0], acc[i][j][1]);
            float2 v1 = make_float2(acc[i][j][2], acc[i][j][3]);
            *(float2*)(C + (size_t)row * 512 + col) = v0;
            *(float2*)(C + (size_t)(row + 8) * 512 + col) = v1;
        }
    }
}

// ---------------- QK_samp -> M (batch-sliced) -------------------------------------
__global__ __launch_bounds__(256) void qkm3_kernel(const int* __restrict__ isamp,
                                                   int boff)
{
    int gw   = ((boff + blockIdx.x) * 256 + threadIdx.x) >> 5;
    int lane = threadIdx.x & 31;
    int l = gw & (L_ - 1);
    int b = gw >> 12;

    const float4* qb = (const float4*)(g_Q + ((size_t)(b * L_ + l)) * DM_);
    float4 q0 = qb[lane], q1 = qb[lane + 32], q2 = qb[lane + 64], q3 = qb[lane + 96];

    float smax0 = -CUDART_INF_F, smax1 = -CUDART_INF_F, smax2 = -CUDART_INF_F, smax3 = -CUDART_INF_F;
    float ssum0 = 0.f, ssum1 = 0.f, ssum2 = 0.f, ssum3 = 0.f;
    const int* ip = isamp + l * U_;

#pragma unroll 2
    for (int u = 0; u < U_; u++) {
        int j = __ldg(ip + u);
        const float4* kb = (const float4*)(g_K + ((size_t)(b * L_ + j)) * DM_);
        float4 k0 = kb[lane], k1 = kb[lane + 32], k2 = kb[lane + 64], k3 = kb[lane + 96];
        float s0 = q0.x * k0.x; s0 = fmaf(q0.y, k0.y, s0); s0 = fmaf(q0.z, k0.z, s0); s0 = fmaf(q0.w, k0.w, s0);
        float s1 = q1.x * k1.x; s1 = fmaf(q1.y, k1.y, s1); s1 = fmaf(q1.z, k1.z, s1); s1 = fmaf(q1.w, k1.w, s1);
        float s2 = q2.x * k2.x; s2 = fmaf(q2.y, k2.y, s2); s2 = fmaf(q2.z, k2.z, s2); s2 = fmaf(q2.w, k2.w, s2);
        float s3 = q3.x * k3.x; s3 = fmaf(q3.y, k3.y, s3); s3 = fmaf(q3.z, k3.z, s3); s3 = fmaf(q3.w, k3.w, s3);
#pragma unroll
        for (int m = 1; m <= 8; m <<= 1) {
            s0 += __shfl_xor_sync(0xffffffffu, s0, m);
            s1 += __shfl_xor_sync(0xffffffffu, s1, m);
            s2 += __shfl_xor_sync(0xffffffffu, s2, m);
            s3 += __shfl_xor_sync(0xffffffffu, s3, m);
        }
        smax0 = fmaxf(smax0, s0); ssum0 += s0;
        smax1 = fmaxf(smax1, s1); ssum1 += s1;
        smax2 = fmaxf(smax2, s2); ssum2 += s2;
        smax3 = fmaxf(smax3, s3); ssum3 += s3;
    }
    if ((lane & 15) == 0) {
        int g = lane >> 4;
        size_t base = ((size_t)b * 8) * L_ + l;
        g_M[base + (size_t)(g + 0) * L_] = smax0 - ssum0 * (1.0f / U_);
        g_M[base + (size_t)(g + 2) * L_] = smax1 - ssum1 * (1.0f / U_);
        g_M[base + (size_t)(g + 4) * L_] = smax2 - ssum2 * (1.0f / U_);
        g_M[base + (size_t)(g + 6) * L_] = smax3 - ssum3 * (1.0f / U_);
    }
}

// ---------------- top-k phase A (bh-sliced) ---------------------------------------
__global__ __launch_bounds__(256) void topkA_kernel(int bhoff)
{
    int slice = blockIdx.x, bh = bhoff + blockIdx.y;
    __shared__ float sv[512];
    __shared__ float wv[8];
    __shared__ int   wi[8];
    int tid = threadIdx.x, lane = tid & 31, w = tid >> 5;

    sv[tid]       = g_M[bh * L_ + slice * 512 + tid];
    sv[tid + 256] = g_M[bh * L_ + slice * 512 + tid + 256];
    __syncthreads();

    for (int it = 0; it < U_; it++) {
        float v0 = sv[tid], v1 = sv[tid + 256];
        float bv; int bi;
        if (v1 > v0) { bv = v1; bi = tid + 256; } else { bv = v0; bi = tid; }
#pragma unroll
        for (int o = 16; o > 0; o >>= 1) {
            float ov = __shfl_xor_sync(0xffffffffu, bv, o);
            int   oi = __shfl_xor_sync(0xffffffffu, bi, o);
            if (ov > bv || (ov == bv && oi < bi)) { bv = ov; bi = oi; }
        }
        if (lane == 0) { wv[w] = bv; wi[w] = bi; }
        __syncthreads();
        if (tid == 0) {
            float fv = wv[0]; int fi = wi[0];
#pragma unroll
            for (int k = 1; k < 8; k++) {
                if (wv[k] > fv || (wv[k] == fv && wi[k] < fi)) { fv = wv[k]; fi = wi[k]; }
            }
            sv[fi] = -CUDART_INF_F;
            g_cval[(bh * 8 + slice) * U_ + it] = fv;
            g_cidx[(bh * 8 + slice) * U_ + it] = slice * 512 + fi;
        }
        __syncthreads();
    }
}

// ---------------- top-k phase B (bh-sliced) ---------------------------------------
__global__ __launch_bounds__(256) void topkB_kernel(int bhoff)
{
    int bh = bhoff + blockIdx.x;
    __shared__ float sv[512];
    __shared__ int   si[512];
    __shared__ float wv[8];
    __shared__ int   wi[8];
    int tid = threadIdx.x, lane = tid & 31, w = tid >> 5;

    const int NC = 8 * U_;
#pragma unroll
    for (int r = 0; r < 2; r++) {
        int i = tid + 256 * r;
        if (i < NC) {
            sv[i] = g_cval[bh * NC + i];
            si[i] = g_cidx[bh * NC + i];
        } else if (i < 512) {
            sv[i] = -CUDART_INF_F;
            si[i] = 0x7fffffff;
        }
    }
    __syncthreads();

    for (int it = 0; it < U_; it++) {
        float v0 = sv[tid], v1 = sv[tid + 256];
        int   i0 = si[tid], i1 = si[tid + 256];
        float bv; int bi, bslot;
        if (v1 > v0 || (v1 == v0 && i1 < i0)) { bv = v1; bi = i1; bslot = tid + 256; }
        else                                   { bv = v0; bi = i0; bslot = tid; }
#pragma unroll
        for (int o = 16; o > 0; o >>= 1) {
            float ov = __shfl_xor_sync(0xffffffffu, bv, o);
            int   oi = __shfl_xor_sync(0xffffffffu, bi, o);
            int   os = __shfl_xor_sync(0xffffffffu, bslot, o);
            if (ov > bv || (ov == bv && oi < bi)) { bv = ov; bi = oi; bslot = os; }
        }
        if (lane == 0) { wv[w] = bv; wi[w] = bslot; }
        __syncthreads();
        if (tid == 0) {
            float fv = wv[0]; int fslot = wi[0];
#pragma unroll
            for (int k = 1; k < 8; k++) {
                int s2 = wi[k];
                if (wv[k] > fv || (wv[k] == fv && si[s2] < si[fslot])) { fv = wv[k]; fslot = s2; }
            }
            g_idx[bh * U_ + it] = si[fslot];
            sv[fslot] = -CUDART_INF_F;
            si[fslot] = 0x7fffffff;
        }
        __syncthreads();
    }
}

// ---------------- V mean per (b,h): 1024 threads, 16-way L-split ------------------
__global__ __launch_bounds__(1024) void vmean_kernel(int bhoff)
{
    int bh = bhoff + blockIdx.x;
    int b = bh >> 3, h = bh & 7;
    int tid = threadIdx.x;
    int d = tid & 63, g = tid >> 6;
    float sum = 0.f;
#pragma unroll 4
    for (int l = g; l < L_; l += 16)
        sum += g_V[((size_t)(b * L_ + l)) * DM_ + h * DK_ + d];
    __shared__ float red[16][64];
    red[g][d] = sum;
    __syncthreads();
    if (g == 0) {
        float t = 0.f;
#pragma unroll
        for (int k = 0; k < 16; k++) t += red[k][d];
        g_vmean[bh * 64 + d] = t * (1.0f / L_);
    }
}

// ---------------- obase partials: per-kc buffers, plain stores --------------------
__global__ __launch_bounds__(256) void obase_part(const float* __restrict__ Wfc,
                                                  int boff)
{
    int b = boff + blockIdx.x;
    int kc = blockIdx.y;
    int tid = threadIdx.x;
    __shared__ float vm[128];
    if (tid < 128) vm[tid] = g_vmean[b * 512 + kc * 128 + tid];
    __syncthreads();
    float a0 = 0.f, a1 = 0.f;
    const float2* W2 = (const float2*)Wfc + tid + (size_t)(kc * 128) * 256;
#pragma unroll 8
    for (int r = 0; r < 128; r++) {
        float2 w = __ldg(W2 + (size_t)r * 256);
        float v = vm[r];
        a0 = fmaf(v, w.x, a0);
        a1 = fmaf(v, w.y, a1);
    }
    g_obase4[kc][b * 512 + 2 * tid]     = a0;
    g_obase4[kc][b * 512 + 2 * tid + 1] = a1;
}

__global__ __launch_bounds__(256) void out_assemble(const float* __restrict__ inQ,
                                                    float* __restrict__ out,
                                                    int i4off)
{
    int i4 = i4off + blockIdx.x * 256 + threadIdx.x;
    int b  = i4 >> 19;
    int c4 = i4 & 127;
    float4 x = ((const float4*)inQ)[i4];
#pragma unroll
    for (int kc = 0; kc < 4; kc++) {
        float4 o = __ldg((const float4*)g_obase4[kc] + (b << 7) + c4);
        x.x += o.x; x.y += o.y; x.z += o.z; x.w += o.w;
    }
    ((float4*)out)[i4] = x;
}

// ---------------- sparse attention: 16-lane groups (bh-sliced) --------------------
__global__ __launch_bounds__(256) void attn_partial(int bhoff)
{
    int ch = blockIdx.x, bh = bhoff + blockIdx.y;
    int b = bh >> 3, h = bh & 7;
    int tid = threadIdx.x, lane = tid & 31, w = tid >> 5;
    int grp = lane >> 4, l4 = lane & 15;

    __shared__ float qs[U_ * DK_];
    __shared__ float Ks[64 * 68];
    __shared__ float Vs[64 * 68];

    for (int i = tid; i < U_ * DK_; i += 256) {
        int u = i >> 6, d = i & 63;
        int l = g_idx[bh * U_ + u];
        qs[i] = g_Q[((size_t)(b * L_ + l)) * DM_ + h * DK_ + d];
    }
    __syncthreads();

    const int nu = (w == 0) ? 6 : 5;
    float4 q4[6], a4[6];
    float m[6], ss[6];
#pragma unroll
    for (int k = 0; k < 6; k++) {
        if (k < nu) {
            int u = w + 8 * k;
            q4[k] = *(const float4*)&qs[u * 64 + 4 * l4];
        } else {
            q4[k] = make_float4(0.f, 0.f, 0.f, 0.f);
        }
        m[k] = -CUDART_INF_F; ss[k] = 0.f;
        a4[k] = make_float4(0.f, 0.f, 0.f, 0.f);
    }

    const int jbase0 = ch * CHUNK_;
    for (int t = 0; t < CHUNK_ / 64; t++) {
        __syncthreads();
        int jb = jbase0 + t * 64;
        const float4* Kg = (const float4*)(g_K + ((size_t)(b * L_ + jb)) * DM_ + h * DK_);
        const float4* Vg = (const float4*)(g_V + ((size_t)(b * L_ + jb)) * DM_ + h * DK_);
#pragma unroll
        for (int r = 0; r < 4; r++) {
            int idx = tid + 256 * r;
            int row = idx >> 4, cq = idx & 15;
            float4 kv = Kg[(size_t)row * (DM_ / 4) + cq];
            *(float4*)&Ks[row * 68 + cq * 4] = kv;
            float4 vv = Vg[(size_t)row * (DM_ / 4) + cq];
            *(float4*)&Vs[row * 68 + cq * 4] = vv;
        }
        __syncthreads();

#pragma unroll 2
        for (int jj2 = 0; jj2 < 32; jj2++) {
            int jj = jj2 * 2 + grp;
            float4 k4 = *(const float4*)&Ks[jj * 68 + 4 * l4];
            float4 v4 = *(const float4*)&Vs[jj * 68 + 4 * l4];
            float sc[6];
#pragma unroll
            for (int k = 0; k < 6; k++) {
                float s = q4[k].x * k4.x;
                s = fmaf(q4[k].y, k4.y, s);
                s = fmaf(q4[k].z, k4.z, s);
                s = fmaf(q4[k].w, k4.w, s);
                sc[k] = s;
            }
#pragma unroll
            for (int o = 1; o <= 8; o <<= 1) {
#pragma unroll
                for (int k = 0; k < 6; k++)
                    sc[k] += __shfl_xor_sync(0xffffffffu, sc[k], o);
            }
#pragma unroll
            for (int k = 0; k < 6; k++) {
                float s = sc[k] * 0.125f;
                float mn = fmaxf(m[k], s);
                float ea = __expf(s - mn);
                float eb = __expf(m[k] - mn);
                ss[k] = ss[k] * eb + ea;
                a4[k].x = a4[k].x * eb + ea * v4.x;
                a4[k].y = a4[k].y * eb + ea * v4.y;
                a4[k].z = a4[k].z * eb + ea * v4.z;
                a4[k].w = a4[k].w * eb + ea * v4.w;
                m[k] = mn;
            }
        }
    }

    const int c2 = ch * 2 + grp;
#pragma unroll
    for (int k = 0; k < 6; k++) {
        if (k < nu) {
            int u = w + 8 * k;
            size_t base = ((size_t)(bh * NCH2_ + c2) * U_ + u) * PREC_;
            *(float4*)&g_part[base + 4 * l4] = a4[k];
            if (l4 == 0) { g_part[base + 64] = m[k]; g_part[base + 65] = ss[k]; }
        }
    }
}

// ---------------- combine split-L partials (bh-sliced) ----------------------------
__global__ __launch_bounds__(256) void attn_combine(int bhoff)
{
    int gw = (blockIdx.x * blockDim.x + threadIdx.x) >> 5;
    int lane = threadIdx.x & 31;
    if (gw >= 32 * U_) return;
    int bh = bhoff + gw / U_, u = gw % U_;

    float M = -CUDART_INF_F;
#pragma unroll
    for (int ch = 0; ch < NCH2_; ch++)
        M = fmaxf(M, g_part[((size_t)(bh * NCH2_ + ch) * U_ + u) * PREC_ + 64]);
    float S = 0.f, a0 = 0.f, a1 = 0.f;
#pragma unroll
    for (int ch = 0; ch < NCH2_; ch++) {
        size_t base = ((size_t)(bh * NCH2_ + ch) * U_ + u) * PREC_;
        float f = __expf(g_part[base + 64] - M);
        S  += g_part[base + 65] * f;
        a0 += g_part[base + 2 * lane] * f;
        a1 += g_part[base + 2 * lane + 1] * f;
    }
    float inv = 1.0f / S;
    size_t gv = (size_t)(bh * U_ + u) * 64;
    g_vals[gv + 2 * lane]     = a0 * inv;
    g_vals[gv + 2 * lane + 1] = a1 * inv;
}

__global__ __launch_bounds__(128) void correction_kernel(float* __restrict__ out,
                                                         const float* __restrict__ Wfc,
                                                         int guoff)
{
    int gu = guoff + blockIdx.x;
    int bh = gu / U_;
    int b = bh >> 3, h = bh & 7;
    int l = g_idx[gu];
    int tid = threadIdx.x;

    __shared__ float delta[64];
    if (tid < 64)
        delta[tid] = g_vals[(size_t)gu * 64 + tid] - g_vmean[bh * 64 + tid];
    __syncthreads();

    float4 acc = make_float4(0.f, 0.f, 0.f, 0.f);
    const float4* W4 = (const float4*)Wfc + (size_t)(h * 64) * 128 + tid;
#pragma unroll 8
    for (int k = 0; k < 64; k++) {
        float d = delta[k];
        float4 w = __ldg(W4 + (size_t)k * 128);
        acc.x = fmaf(d, w.x, acc.x);
        acc.y = fmaf(d, w.y, acc.y);
        acc.z = fmaf(d, w.z, acc.z);
        acc.w = fmaf(d, w.w, acc.w);
    }
    float* o = out + ((size_t)(b * L_ + l)) * 512 + tid * 4;
    atomicAdd(o + 0, acc.x);
    atomicAdd(o + 1, acc.y);
    atomicAdd(o + 2, acc.z);
    atomicAdd(o + 3, acc.w);
}

// ---------------- LayerNorm (row-sliced) ------------------------------------------
__global__ __launch_bounds__(128) void ln_kernel(float* __restrict__ out,
                                                 const float* __restrict__ gamma,
                                                 const float* __restrict__ beta,
                                                 int rowoff)
{
    int row = rowoff + blockIdx.x, tid = threadIdx.x;
    float4 x = ((const float4*)out)[(size_t)row * 128 + tid];
    float s  = x.x + x.y + x.z + x.w;
    float sq = x.x * x.x + x.y * x.y + x.z * x.z + x.w * x.w;
#pragma unroll
    for (int o = 16; o > 0; o >>= 1) {
        s  += __shfl_xor_sync(0xffffffffu, s, o);
        sq += __shfl_xor_sync(0xffffffffu, sq, o);
    }
    __shared__ float sh[8];
    int w = tid >> 5, lane = tid & 31;
    if (lane == 0) { sh[w] = s; sh[4 + w] = sq; }
    __syncthreads();
    s  = sh[0] + sh[1] + sh[2] + sh[3];
    sq = sh[4] + sh[5] + sh[6] + sh[7];
    float mu  = s * (1.0f / 512.0f);
    float var = sq * (1.0f / 512.0f) - mu * mu;
    float r   = rsqrtf(var + EPS_);
    float4 gg = ((const float4*)gamma)[tid];
    float4 bb = ((const float4*)beta)[tid];
    float4 y;
    y.x = gg.x * (x.x - mu) * r + bb.x;
    y.y = gg.y * (x.y - mu) * r + bb.y;
    y.z = gg.z * (x.z - mu) * r + bb.z;
    y.w = gg.w * (x.w - mu) * r + bb.w;
    ((float4*)out)[(size_t)row * 128 + tid] = y;
}

// ---------------- launch ------------------------------------------------------------
extern "C" void kernel_launch(void* const* d_in, const int* in_sizes, int n_in,
                              void* d_out, int out_size)
{
    const float* inQ   = (const float*)d_in[0];
    const float* inK   = (const float*)d_in[1];
    const float* inV   = (const float*)d_in[2];
    const float* WQ    = (const float*)d_in[3];
    const float* WK    = (const float*)d_in[4];
    const float* WV    = (const float*)d_in[5];
    const float* Wfc   = (const float*)d_in[6];
    const float* gamma = (const float*)d_in[7];
    const float* beta  = (const float*)d_in[8];
    const int*   isamp = (const int*)d_in[9];
    float* out = (float*)d_out;

    static cudaStream_t s2, s3, s4;
    static cudaEvent_t evGa, evVa, evGb, evVb, evQb, evOAa, evOAb, evH1;
    static bool init = false;
    if (!init) {
        cudaStreamCreateWithFlags(&s2, cudaStreamNonBlocking);
        cudaStreamCreateWithFlags(&s3, cudaStreamNonBlocking);
        cudaStreamCreateWithFlags(&s4, cudaStreamNonBlocking);
        cudaEventCreateWithFlags(&evGa, cudaEventDisableTiming);
        cudaEventCreateWithFlags(&evVa, cudaEventDisableTiming);
        cudaEventCreateWithFlags(&evGb, cudaEventDisableTiming);
        cudaEventCreateWithFlags(&evVb, cudaEventDisableTiming);
        cudaEventCreateWithFlags(&evQb, cudaEventDisableTiming);
        cudaEventCreateWithFlags(&evOAa, cudaEventDisableTiming);
        cudaEventCreateWithFlags(&evOAb, cudaEventDisableTiming);
        cudaEventCreateWithFlags(&evH1, cudaEventDisableTiming);
        cudaFuncSetAttribute(gemm3_hmma, cudaFuncAttributeMaxDynamicSharedMemorySize,
                             GSMEM_BYTES);
        init = true;
    }

    const int cmbBlocks = (32 * U_ * 32 + 255) / 256;

    // ---- main: ALL tensor work back-to-back ----
    transW_kernel<<<dim3(16, 16, 3), 256>>>(WQ, WK, WV);
    gemm3_hmma<<<dim3(4, 128, 2), 256, GSMEM_BYTES>>>(inQ, inK, inV, 0, 0);       // QK b0-3
    cudaEventRecord(evGa, 0);
    gemm3_hmma<<<dim3(4, 128, 1), 256, GSMEM_BYTES>>>(inQ, inK, inV, 2, 0);       // V  b0-3
    cudaEventRecord(evVa, 0);
    gemm3_hmma<<<dim3(4, 128, 2), 256, GSMEM_BYTES>>>(inQ, inK, inV, 0, 16384);   // QK b4-7
    cudaEventRecord(evGb, 0);
    gemm3_hmma<<<dim3(4, 128, 1), 256, GSMEM_BYTES>>>(inQ, inK, inV, 2, 16384);   // V  b4-7
    cudaEventRecord(evVb, 0);

    // ---- s2: V-branch halves ----
    cudaStreamWaitEvent(s2, evVa, 0);
    vmean_kernel<<<32, 1024, 0, s2>>>(0);
    obase_part<<<dim3(4, 4), 256, 0, s2>>>(Wfc, 0);
    out_assemble<<<8192, 256, 0, s2>>>(inQ, out, 0);
    cudaEventRecord(evOAa, s2);
    cudaStreamWaitEvent(s2, evVb, 0);
    vmean_kernel<<<32, 1024, 0, s2>>>(32);
    obase_part<<<dim3(4, 4), 256, 0, s2>>>(Wfc, 4);
    out_assemble<<<8192, 256, 0, s2>>>(inQ, out, 8192 * 256);
    cudaEventRecord(evOAb, s2);

    // ---- s4: qkm second half (overlaps gemmV b4-7) ----
    cudaStreamWaitEvent(s4, evGb, 0);
    qkm3_kernel<<<2048, 256, 0, s4>>>(isamp, 2048);
    cudaEventRecord(evQb, s4);

    // ---- s3: first-half tail (bh 0-31, rows 0-16383) ----
    cudaStreamWaitEvent(s3, evGa, 0);
    qkm3_kernel<<<2048, 256, 0, s3>>>(isamp, 0);
    topkA_kernel<<<dim3(8, 32), 256, 0, s3>>>(0);
    topkB_kernel<<<32, 256, 0, s3>>>(0);
    cudaStreamWaitEvent(s3, evVa, 0);
    attn_partial<<<dim3(NCH_, 32), 256, 0, s3>>>(0);
    attn_combine<<<cmbBlocks, 256, 0, s3>>>(0);
    cudaStreamWaitEvent(s3, evOAa, 0);
    correction_kernel<<<32 * U_, 128, 0, s3>>>(out, Wfc, 0);
    ln_kernel<<<16384, 128, 0, s3>>>(out, gamma, beta, 0);
    cudaEventRecord(evH1, s3);

    // ---- main: second-half tail (bh 32-63, rows 16384-32767) ----
    cudaStreamWaitEvent(0, evQb, 0);
    topkA_kernel<<<dim3(8, 32), 256>>>(32);
    topkB_kernel<<<32, 256>>>(32);
    attn_partial<<<dim3(NCH_, 32), 256>>>(32);
    attn_combine<<<cmbBlocks, 256>>>(32);
    cudaStreamWaitEvent(0, evOAb, 0);
    correction_kernel<<<32 * U_, 128>>>(out, Wfc, 32 * U_);
    ln_kernel<<<16384, 128>>>(out, gamma, beta, 16384);

    // ---- join ----
    cudaStreamWaitEvent(0, evH1, 0);
}